// round 3
// baseline (speedup 1.0000x reference)
#include <cuda_runtime.h>
#include <cuda_bf16.h>
#include <cstdint>

#define BB 2
#define SS 2048
#define DD 1024
#define HH 16
#define HD 64
#define MM (BB*SS)
#define QSCALE (0.125f * 1.44269504088896340736f)

// ---------------- static scratch ----------------
__device__ __nv_bfloat16 g_xh[MM*DD], g_xl[MM*DD];
__device__ __nv_bfloat16 g_qh[MM*DD], g_ql[MM*DD];
__device__ __nv_bfloat16 g_kh[MM*DD], g_kl[MM*DD];
__device__ __nv_bfloat16 g_vh[MM*DD], g_vl[MM*DD];
__device__ __nv_bfloat16 g_wqh[DD*DD], g_wql[DD*DD];
__device__ __nv_bfloat16 g_wkh[DD*DD], g_wkl[DD*DD];
__device__ __nv_bfloat16 g_wvh[DD*DD], g_wvl[DD*DD];

// ---------------- helpers ----------------
__device__ __forceinline__ float ex2(float x) {
    float y; asm("ex2.approx.f32 %0, %1;" : "=f"(y) : "f"(x)); return y;
}
__device__ __forceinline__ uint32_t packbf(float a, float b) {
    __nv_bfloat16 ha = __float2bfloat16_rn(a);
    __nv_bfloat16 hb = __float2bfloat16_rn(b);
    return ((uint32_t)__bfloat16_as_ushort(hb) << 16) | (uint32_t)__bfloat16_as_ushort(ha);
}
__device__ __forceinline__ void packhl(float a, float b, uint32_t& hi, uint32_t& lo) {
    __nv_bfloat16 ha = __float2bfloat16_rn(a);
    __nv_bfloat16 hb = __float2bfloat16_rn(b);
    float ra = a - __bfloat162float(ha);
    float rb = b - __bfloat162float(hb);
    __nv_bfloat16 la = __float2bfloat16_rn(ra);
    __nv_bfloat16 lb = __float2bfloat16_rn(rb);
    hi = ((uint32_t)__bfloat16_as_ushort(hb) << 16) | (uint32_t)__bfloat16_as_ushort(ha);
    lo = ((uint32_t)__bfloat16_as_ushort(lb) << 16) | (uint32_t)__bfloat16_as_ushort(la);
}
__device__ __forceinline__ void ldsm_x4(uint32_t* r, uint32_t addr) {
    asm volatile("ldmatrix.sync.aligned.m8n8.x4.shared.b16 {%0,%1,%2,%3}, [%4];"
        : "=r"(r[0]), "=r"(r[1]), "=r"(r[2]), "=r"(r[3]) : "r"(addr));
}
__device__ __forceinline__ void ldsm_x2(uint32_t* r, uint32_t addr) {
    asm volatile("ldmatrix.sync.aligned.m8n8.x2.shared.b16 {%0,%1}, [%2];"
        : "=r"(r[0]), "=r"(r[1]) : "r"(addr));
}
__device__ __forceinline__ void ldsm_x2t(uint32_t* r, uint32_t addr) {
    asm volatile("ldmatrix.sync.aligned.m8n8.x2.trans.shared.b16 {%0,%1}, [%2];"
        : "=r"(r[0]), "=r"(r[1]) : "r"(addr));
}
__device__ __forceinline__ void mma16816(float* d, const uint32_t* a, const uint32_t* b) {
    asm volatile(
        "mma.sync.aligned.m16n8k16.row.col.f32.bf16.bf16.f32 "
        "{%0,%1,%2,%3}, {%4,%5,%6,%7}, {%8,%9}, {%0,%1,%2,%3};"
        : "+f"(d[0]), "+f"(d[1]), "+f"(d[2]), "+f"(d[3])
        : "r"(a[0]), "r"(a[1]), "r"(a[2]), "r"(a[3]), "r"(b[0]), "r"(b[1]));
}

// ---------------- split fp32 -> bf16 hi/lo ----------------
__global__ void split_kernel(const float* __restrict__ in,
                             __nv_bfloat16* __restrict__ hi,
                             __nv_bfloat16* __restrict__ lo, int n)
{
    int i = (blockIdx.x * blockDim.x + threadIdx.x) * 4;
    if (i >= n) return;
    float4 v = *(const float4*)(in + i);
    uint32_t h0, l0, h1, l1;
    packhl(v.x, v.y, h0, l0);
    packhl(v.z, v.w, h1, l1);
    *(uint2*)(hi + i) = make_uint2(h0, h1);
    *(uint2*)(lo + i) = make_uint2(l0, l1);
}

// ---------------- GEMM: C = (A@W + bias)*scale, split-bf16 x3 ----------------
// A: [MM, DD] (hi/lo), W: [DD, DD] (hi/lo). Output scattered to [B,H,S,HD] as hi/lo bf16.
#define AST 40    // A smem row stride (halves)
#define BST 136   // B smem row stride (halves)

__global__ __launch_bounds__(256, 1)
void gemm_bf16x3(const __nv_bfloat16* __restrict__ Ah, const __nv_bfloat16* __restrict__ Al,
                 const __nv_bfloat16* __restrict__ Wh, const __nv_bfloat16* __restrict__ Wl,
                 const float* __restrict__ bias,
                 __nv_bfloat16* __restrict__ Ch, __nv_bfloat16* __restrict__ Cl,
                 float scale)
{
    __shared__ __nv_bfloat16 sAh[128*AST], sAl[128*AST];
    __shared__ __nv_bfloat16 sBh[32*BST],  sBl[32*BST];

    const int tid  = threadIdx.x;
    const int lane = tid & 31;
    const int w    = tid >> 5;
    const int wm   = w >> 2;          // 0..1 (64 rows each)
    const int wn   = w & 3;           // 0..3 (32 cols each)
    const int m0   = blockIdx.y * 128;
    const int n0   = blockIdx.x * 128;

    const uint32_t sAh_b = (uint32_t)__cvta_generic_to_shared(sAh);
    const uint32_t sAl_b = (uint32_t)__cvta_generic_to_shared(sAl);
    const uint32_t sBh_b = (uint32_t)__cvta_generic_to_shared(sBh);
    const uint32_t sBl_b = (uint32_t)__cvta_generic_to_shared(sBl);

    float acc[4][4][4];
    #pragma unroll
    for (int i = 0; i < 4; i++)
        #pragma unroll
        for (int j = 0; j < 4; j++)
            #pragma unroll
            for (int k = 0; k < 4; k++) acc[i][j][k] = 0.0f;

    for (int k0 = 0; k0 < DD; k0 += 32) {
        __syncthreads();
        // load A tiles (128x32) and B tiles (32x128), hi+lo
        #pragma unroll
        for (int j = 0; j < 2; j++) {
            int u = tid * 2 + j;
            int ar = u >> 2, as = (u & 3) * 8;              // A: 4 uint4 per row
            size_t ag = (size_t)(m0 + ar) * DD + k0 + as;
            *(uint4*)&sAh[ar*AST + as] = *(const uint4*)(Ah + ag);
            *(uint4*)&sAl[ar*AST + as] = *(const uint4*)(Al + ag);
            int br = u >> 4, bs = (u & 15) * 8;             // B: 16 uint4 per row
            size_t bg = (size_t)(k0 + br) * DD + n0 + bs;
            *(uint4*)&sBh[br*BST + bs] = *(const uint4*)(Wh + bg);
            *(uint4*)&sBl[br*BST + bs] = *(const uint4*)(Wl + bg);
        }
        __syncthreads();

        #pragma unroll
        for (int kc = 0; kc < 2; kc++) {
            uint32_t ah[4][4], al[4][4], bh[4][2], bl[4][2];
            #pragma unroll
            for (int mt = 0; mt < 4; mt++) {
                uint32_t off = (uint32_t)(((wm*64 + mt*16 + (lane & 15)) * AST
                                           + kc*16 + (lane >> 4) * 8) * 2);
                ldsm_x4(ah[mt], sAh_b + off);
                ldsm_x4(al[mt], sAl_b + off);
            }
            #pragma unroll
            for (int nt = 0; nt < 4; nt++) {
                uint32_t off = (uint32_t)(((kc*16 + (lane & 15)) * BST
                                           + wn*32 + nt*8) * 2);
                ldsm_x2t(bh[nt], sBh_b + off);
                ldsm_x2t(bl[nt], sBl_b + off);
            }
            #pragma unroll
            for (int mt = 0; mt < 4; mt++)
                #pragma unroll
                for (int nt = 0; nt < 4; nt++) {
                    mma16816(acc[mt][nt], ah[mt], bh[nt]);
                    mma16816(acc[mt][nt], ah[mt], bl[nt]);
                    mma16816(acc[mt][nt], al[mt], bh[nt]);
                }
        }
    }

    // epilogue: bias+scale, split hi/lo, scatter to [B,H,S,HD]
    const int g = lane >> 2, tig = lane & 3;
    #pragma unroll
    for (int mt = 0; mt < 4; mt++)
        #pragma unroll
        for (int nt = 0; nt < 4; nt++) {
            int col = n0 + wn*32 + nt*8 + tig*2;
            int h = col >> 6, d = col & 63;
            float b0 = bias[col], b1 = bias[col + 1];
            #pragma unroll
            for (int rr = 0; rr < 2; rr++) {
                int m = m0 + wm*64 + mt*16 + g + rr*8;
                int b = m >> 11, s = m & 2047;
                size_t off = ((size_t)((b*HH + h)*SS + s)) * HD + d;
                float v0 = (acc[mt][nt][rr*2 + 0] + b0) * scale;
                float v1 = (acc[mt][nt][rr*2 + 1] + b1) * scale;
                uint32_t hp, lp;
                packhl(v0, v1, hp, lp);
                *(uint32_t*)(Ch + off) = hp;
                *(uint32_t*)(Cl + off) = lp;
            }
        }
}

// ---------------- flash attention with bf16x3 mma ----------------
// CTA: 128 q-rows of one (b,h); 8 warps x 16 rows. KV tiles of 64.
#define KST 72    // K/V smem row stride (halves)

__global__ __launch_bounds__(256, 1)
void attn_mma(const __nv_bfloat16* __restrict__ qh, const __nv_bfloat16* __restrict__ ql,
              const __nv_bfloat16* __restrict__ kh, const __nv_bfloat16* __restrict__ kl,
              const __nv_bfloat16* __restrict__ vh, const __nv_bfloat16* __restrict__ vl,
              float* __restrict__ out)
{
    __shared__ __nv_bfloat16 smbuf[4*64*KST];
    __nv_bfloat16* Kh = smbuf;
    __nv_bfloat16* Kl = smbuf + 64*KST;
    __nv_bfloat16* Vh = smbuf + 2*64*KST;
    __nv_bfloat16* Vl = smbuf + 3*64*KST;
    const uint32_t Kh_b = (uint32_t)__cvta_generic_to_shared(Kh);
    const uint32_t Kl_b = (uint32_t)__cvta_generic_to_shared(Kl);
    const uint32_t Vh_b = (uint32_t)__cvta_generic_to_shared(Vh);
    const uint32_t Vl_b = (uint32_t)__cvta_generic_to_shared(Vl);

    const int tid  = threadIdx.x;
    const int lane = tid & 31;
    const int w    = tid >> 5;
    const int q0   = blockIdx.x * 128;
    const int bhI  = blockIdx.y;
    const int g    = lane >> 2, tig = lane & 3;

    const size_t hd_base = (size_t)bhI * SS * HD;

    // ---- load Q fragments (staged through smem, hi pass then lo pass) ----
    uint32_t qa_h[4][4], qa_l[4][4];
    {
        const uint32_t st_b = Kh_b;  // reuse Kh+Kl region (128*KST halves)
        __nv_bfloat16* stage = Kh;
        #pragma unroll
        for (int pass = 0; pass < 2; pass++) {
            const __nv_bfloat16* src = (pass == 0 ? qh : ql) + hd_base + (size_t)q0 * HD;
            for (int u = tid; u < 1024; u += 256) {
                int r = u >> 3, s8 = (u & 7) * 8;
                *(uint4*)&stage[r*KST + s8] = *(const uint4*)(src + r*HD + s8);
            }
            __syncthreads();
            #pragma unroll
            for (int kc = 0; kc < 4; kc++) {
                uint32_t off = (uint32_t)(((w*16 + (lane & 15)) * KST
                                           + kc*16 + (lane >> 4) * 8) * 2);
                if (pass == 0) ldsm_x4(qa_h[kc], st_b + off);
                else           ldsm_x4(qa_l[kc], st_b + off);
            }
            __syncthreads();
        }
    }

    float m0 = -1e4f, m1 = -1e4f, l0 = 0.0f, l1 = 0.0f;
    float o[8][4];
    #pragma unroll
    for (int nt = 0; nt < 8; nt++)
        #pragma unroll
        for (int j = 0; j < 4; j++) o[nt][j] = 0.0f;

    for (int kt = 0; kt < SS / 64; kt++) {
        __syncthreads();
        // load K,V tiles (64x64 each, hi+lo)
        #pragma unroll
        for (int j = 0; j < 2; j++) {
            int u = tid * 2 + j;
            int r = u >> 3, s8 = (u & 7) * 8;
            size_t gm = hd_base + (size_t)(kt*64 + r) * HD + s8;
            int so = r*KST + s8;
            *(uint4*)&Kh[so] = *(const uint4*)(kh + gm);
            *(uint4*)&Kl[so] = *(const uint4*)(kl + gm);
            *(uint4*)&Vh[so] = *(const uint4*)(vh + gm);
            *(uint4*)&Vl[so] = *(const uint4*)(vl + gm);
        }
        __syncthreads();

        // ---- S = Q K^T ----
        float sacc[8][4];
        #pragma unroll
        for (int nt = 0; nt < 8; nt++)
            #pragma unroll
            for (int j = 0; j < 4; j++) sacc[nt][j] = 0.0f;

        #pragma unroll
        for (int kc = 0; kc < 4; kc++) {
            uint32_t kbh[8][2], kbl[8][2];
            #pragma unroll
            for (int nt = 0; nt < 8; nt++) {
                // non-trans ldmatrix on row-major K gives the B=K^T fragment
                uint32_t off = (uint32_t)(((nt*8 + (lane & 7)) * KST
                                           + kc*16 + (lane & 8)) * 2);
                ldsm_x2(kbh[nt], Kh_b + off);
                ldsm_x2(kbl[nt], Kl_b + off);
            }
            #pragma unroll
            for (int nt = 0; nt < 8; nt++) {
                mma16816(sacc[nt], qa_h[kc], kbh[nt]);
                mma16816(sacc[nt], qa_h[kc], kbl[nt]);
                mma16816(sacc[nt], qa_l[kc], kbh[nt]);
            }
        }

        // ---- online softmax (S already in log2 units) ----
        float rm0 = -1e30f, rm1 = -1e30f;
        #pragma unroll
        for (int nt = 0; nt < 8; nt++) {
            rm0 = fmaxf(rm0, fmaxf(sacc[nt][0], sacc[nt][1]));
            rm1 = fmaxf(rm1, fmaxf(sacc[nt][2], sacc[nt][3]));
        }
        rm0 = fmaxf(rm0, __shfl_xor_sync(0xffffffffu, rm0, 1));
        rm0 = fmaxf(rm0, __shfl_xor_sync(0xffffffffu, rm0, 2));
        rm1 = fmaxf(rm1, __shfl_xor_sync(0xffffffffu, rm1, 1));
        rm1 = fmaxf(rm1, __shfl_xor_sync(0xffffffffu, rm1, 2));
        float nm0 = fmaxf(m0, rm0), nm1 = fmaxf(m1, rm1);
        float a0 = ex2(m0 - nm0), a1 = ex2(m1 - nm1);
        float rs0 = 0.0f, rs1 = 0.0f;
        #pragma unroll
        for (int nt = 0; nt < 8; nt++) {
            sacc[nt][0] = ex2(sacc[nt][0] - nm0);
            sacc[nt][1] = ex2(sacc[nt][1] - nm0);
            sacc[nt][2] = ex2(sacc[nt][2] - nm1);
            sacc[nt][3] = ex2(sacc[nt][3] - nm1);
            rs0 += sacc[nt][0] + sacc[nt][1];
            rs1 += sacc[nt][2] + sacc[nt][3];
        }
        rs0 += __shfl_xor_sync(0xffffffffu, rs0, 1);
        rs0 += __shfl_xor_sync(0xffffffffu, rs0, 2);
        rs1 += __shfl_xor_sync(0xffffffffu, rs1, 1);
        rs1 += __shfl_xor_sync(0xffffffffu, rs1, 2);
        l0 = l0 * a0 + rs0;  m0 = nm0;
        l1 = l1 * a1 + rs1;  m1 = nm1;
        #pragma unroll
        for (int nt = 0; nt < 8; nt++) {
            o[nt][0] *= a0; o[nt][1] *= a0;
            o[nt][2] *= a1; o[nt][3] *= a1;
        }

        // ---- P fragments (C-layout -> A-layout), hi/lo split ----
        uint32_t ph[4][4], pl[4][4];
        #pragma unroll
        for (int kc = 0; kc < 4; kc++) {
            packhl(sacc[2*kc][0],   sacc[2*kc][1],   ph[kc][0], pl[kc][0]);
            packhl(sacc[2*kc][2],   sacc[2*kc][3],   ph[kc][1], pl[kc][1]);
            packhl(sacc[2*kc+1][0], sacc[2*kc+1][1], ph[kc][2], pl[kc][2]);
            packhl(sacc[2*kc+1][2], sacc[2*kc+1][3], ph[kc][3], pl[kc][3]);
        }

        // ---- O += P V ----
        #pragma unroll
        for (int kc = 0; kc < 4; kc++) {
            uint32_t vbh[8][2], vbl[8][2];
            #pragma unroll
            for (int nt = 0; nt < 8; nt++) {
                uint32_t off = (uint32_t)(((kc*16 + (lane & 15)) * KST + nt*8) * 2);
                ldsm_x2t(vbh[nt], Vh_b + off);
                ldsm_x2t(vbl[nt], Vl_b + off);
            }
            #pragma unroll
            for (int nt = 0; nt < 8; nt++) {
                mma16816(o[nt], ph[kc], vbh[nt]);
                mma16816(o[nt], ph[kc], vbl[nt]);
                mma16816(o[nt], pl[kc], vbh[nt]);
            }
        }
    }

    // ---- epilogue: normalize, write [B,S,D] fp32 ----
    const int b = bhI >> 4, h = bhI & 15;
    const float inv0 = 1.0f / l0, inv1 = 1.0f / l1;
    const int s0 = q0 + w*16 + g;
    #pragma unroll
    for (int nt = 0; nt < 8; nt++) {
        int d = h*64 + nt*8 + tig*2;
        float2 r0 = make_float2(o[nt][0] * inv0, o[nt][1] * inv0);
        float2 r1 = make_float2(o[nt][2] * inv1, o[nt][3] * inv1);
        *(float2*)(out + ((size_t)(b*SS + s0))     * DD + d) = r0;
        *(float2*)(out + ((size_t)(b*SS + s0 + 8)) * DD + d) = r1;
    }
}

// ---------------------------------------------------------------------------
extern "C" void kernel_launch(void* const* d_in, const int* in_sizes, int n_in,
                              void* d_out, int out_size)
{
    (void)in_sizes; (void)n_in; (void)out_size;
    const float* x  = (const float*)d_in[0];
    const float* Wq = (const float*)d_in[1];
    const float* bq = (const float*)d_in[2];
    const float* Wk = (const float*)d_in[3];
    const float* bk = (const float*)d_in[4];
    const float* Wv = (const float*)d_in[5];
    const float* bv = (const float*)d_in[6];
    float* out = (float*)d_out;

    __nv_bfloat16 *xh, *xl, *wqh, *wql, *wkh, *wkl, *wvh, *wvl;
    __nv_bfloat16 *qhp, *qlp, *khp, *klp, *vhp, *vlp;
    cudaGetSymbolAddress((void**)&xh,  g_xh);  cudaGetSymbolAddress((void**)&xl,  g_xl);
    cudaGetSymbolAddress((void**)&wqh, g_wqh); cudaGetSymbolAddress((void**)&wql, g_wql);
    cudaGetSymbolAddress((void**)&wkh, g_wkh); cudaGetSymbolAddress((void**)&wkl, g_wkl);
    cudaGetSymbolAddress((void**)&wvh, g_wvh); cudaGetSymbolAddress((void**)&wvl, g_wvl);
    cudaGetSymbolAddress((void**)&qhp, g_qh);  cudaGetSymbolAddress((void**)&qlp, g_ql);
    cudaGetSymbolAddress((void**)&khp, g_kh);  cudaGetSymbolAddress((void**)&klp, g_kl);
    cudaGetSymbolAddress((void**)&vhp, g_vh);  cudaGetSymbolAddress((void**)&vlp, g_vl);

    split_kernel<<<(MM*DD)/4/256, 256>>>(x,  xh,  xl,  MM*DD);
    split_kernel<<<(DD*DD)/4/256, 256>>>(Wq, wqh, wql, DD*DD);
    split_kernel<<<(DD*DD)/4/256, 256>>>(Wk, wkh, wkl, DD*DD);
    split_kernel<<<(DD*DD)/4/256, 256>>>(Wv, wvh, wvl, DD*DD);

    dim3 ggrid(DD/128, MM/128);   // (8, 32)
    gemm_bf16x3<<<ggrid, 256>>>(xh, xl, wqh, wql, bq, qhp, qlp, QSCALE);
    gemm_bf16x3<<<ggrid, 256>>>(xh, xl, wkh, wkl, bk, khp, klp, 1.0f);
    gemm_bf16x3<<<ggrid, 256>>>(xh, xl, wvh, wvl, bv, vhp, vlp, 1.0f);

    dim3 agrid(SS/128, BB*HH);    // (16, 32)
    attn_mma<<<agrid, 256>>>(qhp, qlp, khp, klp, vhp, vlp, out);
}

// round 4
// speedup vs baseline: 1.0026x; 1.0026x over previous
#include <cuda_runtime.h>
#include <cuda_bf16.h>
#include <cstdint>

#define BB 2
#define SS 2048
#define DD 1024
#define HH 16
#define HD 64
#define MM (BB*SS)
#define QSCALE (0.125f * 1.44269504088896340736f)

// ---------------- static scratch ----------------
__device__ __nv_bfloat16 g_xh[MM*DD], g_xl[MM*DD];
__device__ __nv_bfloat16 g_qh[MM*DD], g_ql[MM*DD];
__device__ __nv_bfloat16 g_kh[MM*DD], g_kl[MM*DD];
__device__ __nv_bfloat16 g_vh[MM*DD], g_vl[MM*DD];
__device__ __nv_bfloat16 g_wqh[DD*DD], g_wql[DD*DD];
__device__ __nv_bfloat16 g_wkh[DD*DD], g_wkl[DD*DD];
__device__ __nv_bfloat16 g_wvh[DD*DD], g_wvl[DD*DD];

// ---------------- helpers ----------------
__device__ __forceinline__ float ex2(float x) {
    float y; asm("ex2.approx.f32 %0, %1;" : "=f"(y) : "f"(x)); return y;
}
__device__ __forceinline__ uint32_t packbf(float a, float b) {
    __nv_bfloat16 ha = __float2bfloat16_rn(a);
    __nv_bfloat16 hb = __float2bfloat16_rn(b);
    return ((uint32_t)__bfloat16_as_ushort(hb) << 16) | (uint32_t)__bfloat16_as_ushort(ha);
}
__device__ __forceinline__ void packhl(float a, float b, uint32_t& hi, uint32_t& lo) {
    __nv_bfloat16 ha = __float2bfloat16_rn(a);
    __nv_bfloat16 hb = __float2bfloat16_rn(b);
    float ra = a - __bfloat162float(ha);
    float rb = b - __bfloat162float(hb);
    __nv_bfloat16 la = __float2bfloat16_rn(ra);
    __nv_bfloat16 lb = __float2bfloat16_rn(rb);
    hi = ((uint32_t)__bfloat16_as_ushort(hb) << 16) | (uint32_t)__bfloat16_as_ushort(ha);
    lo = ((uint32_t)__bfloat16_as_ushort(lb) << 16) | (uint32_t)__bfloat16_as_ushort(la);
}
__device__ __forceinline__ void ldsm_x4(uint32_t* r, uint32_t addr) {
    asm volatile("ldmatrix.sync.aligned.m8n8.x4.shared.b16 {%0,%1,%2,%3}, [%4];"
        : "=r"(r[0]), "=r"(r[1]), "=r"(r[2]), "=r"(r[3]) : "r"(addr));
}
__device__ __forceinline__ void ldsm_x2(uint32_t* r, uint32_t addr) {
    asm volatile("ldmatrix.sync.aligned.m8n8.x2.shared.b16 {%0,%1}, [%2];"
        : "=r"(r[0]), "=r"(r[1]) : "r"(addr));
}
__device__ __forceinline__ void ldsm_x2t(uint32_t* r, uint32_t addr) {
    asm volatile("ldmatrix.sync.aligned.m8n8.x2.trans.shared.b16 {%0,%1}, [%2];"
        : "=r"(r[0]), "=r"(r[1]) : "r"(addr));
}
__device__ __forceinline__ void mma16816(float* d, const uint32_t* a, const uint32_t* b) {
    asm volatile(
        "mma.sync.aligned.m16n8k16.row.col.f32.bf16.bf16.f32 "
        "{%0,%1,%2,%3}, {%4,%5,%6,%7}, {%8,%9}, {%0,%1,%2,%3};"
        : "+f"(d[0]), "+f"(d[1]), "+f"(d[2]), "+f"(d[3])
        : "r"(a[0]), "r"(a[1]), "r"(a[2]), "r"(a[3]), "r"(b[0]), "r"(b[1]));
}

// ---------------- split fp32 -> bf16 hi/lo ----------------
__global__ void split_kernel(const float* __restrict__ in,
                             __nv_bfloat16* __restrict__ hi,
                             __nv_bfloat16* __restrict__ lo, int n)
{
    int i = (blockIdx.x * blockDim.x + threadIdx.x) * 4;
    if (i >= n) return;
    float4 v = *(const float4*)(in + i);
    uint32_t h0, l0, h1, l1;
    packhl(v.x, v.y, h0, l0);
    packhl(v.z, v.w, h1, l1);
    *(uint2*)(hi + i) = make_uint2(h0, h1);
    *(uint2*)(lo + i) = make_uint2(l0, l1);
}

// ---------------- GEMM: C = (A@W + bias)*scale, split-bf16 x3 ----------------
// A: [MM, DD] (hi/lo), W: [DD, DD] (hi/lo). Output scattered to [B,H,S,HD] as hi/lo bf16.
#define AST 40    // A smem row stride (halves)
#define BST 136   // B smem row stride (halves)

__global__ __launch_bounds__(256, 1)
void gemm_bf16x3(const __nv_bfloat16* __restrict__ Ah, const __nv_bfloat16* __restrict__ Al,
                 const __nv_bfloat16* __restrict__ Wh, const __nv_bfloat16* __restrict__ Wl,
                 const float* __restrict__ bias,
                 __nv_bfloat16* __restrict__ Ch, __nv_bfloat16* __restrict__ Cl,
                 float scale)
{
    __shared__ __nv_bfloat16 sAh[128*AST], sAl[128*AST];
    __shared__ __nv_bfloat16 sBh[32*BST],  sBl[32*BST];

    const int tid  = threadIdx.x;
    const int lane = tid & 31;
    const int w    = tid >> 5;
    const int wm   = w >> 2;          // 0..1 (64 rows each)
    const int wn   = w & 3;           // 0..3 (32 cols each)
    const int m0   = blockIdx.y * 128;
    const int n0   = blockIdx.x * 128;

    const uint32_t sAh_b = (uint32_t)__cvta_generic_to_shared(sAh);
    const uint32_t sAl_b = (uint32_t)__cvta_generic_to_shared(sAl);
    const uint32_t sBh_b = (uint32_t)__cvta_generic_to_shared(sBh);
    const uint32_t sBl_b = (uint32_t)__cvta_generic_to_shared(sBl);

    float acc[4][4][4];
    #pragma unroll
    for (int i = 0; i < 4; i++)
        #pragma unroll
        for (int j = 0; j < 4; j++)
            #pragma unroll
            for (int k = 0; k < 4; k++) acc[i][j][k] = 0.0f;

    for (int k0 = 0; k0 < DD; k0 += 32) {
        __syncthreads();
        // load A tiles (128x32) and B tiles (32x128), hi+lo
        #pragma unroll
        for (int j = 0; j < 2; j++) {
            int u = tid * 2 + j;
            int ar = u >> 2, as = (u & 3) * 8;              // A: 4 uint4 per row
            size_t ag = (size_t)(m0 + ar) * DD + k0 + as;
            *(uint4*)&sAh[ar*AST + as] = *(const uint4*)(Ah + ag);
            *(uint4*)&sAl[ar*AST + as] = *(const uint4*)(Al + ag);
            int br = u >> 4, bs = (u & 15) * 8;             // B: 16 uint4 per row
            size_t bg = (size_t)(k0 + br) * DD + n0 + bs;
            *(uint4*)&sBh[br*BST + bs] = *(const uint4*)(Wh + bg);
            *(uint4*)&sBl[br*BST + bs] = *(const uint4*)(Wl + bg);
        }
        __syncthreads();

        #pragma unroll
        for (int kc = 0; kc < 2; kc++) {
            uint32_t ah[4][4], al[4][4], bh[4][2], bl[4][2];
            #pragma unroll
            for (int mt = 0; mt < 4; mt++) {
                uint32_t off = (uint32_t)(((wm*64 + mt*16 + (lane & 15)) * AST
                                           + kc*16 + (lane >> 4) * 8) * 2);
                ldsm_x4(ah[mt], sAh_b + off);
                ldsm_x4(al[mt], sAl_b + off);
            }
            #pragma unroll
            for (int nt = 0; nt < 4; nt++) {
                uint32_t off = (uint32_t)(((kc*16 + (lane & 15)) * BST
                                           + wn*32 + nt*8) * 2);
                ldsm_x2t(bh[nt], sBh_b + off);
                ldsm_x2t(bl[nt], sBl_b + off);
            }
            #pragma unroll
            for (int mt = 0; mt < 4; mt++)
                #pragma unroll
                for (int nt = 0; nt < 4; nt++) {
                    mma16816(acc[mt][nt], ah[mt], bh[nt]);
                    mma16816(acc[mt][nt], ah[mt], bl[nt]);
                    mma16816(acc[mt][nt], al[mt], bh[nt]);
                }
        }
    }

    // epilogue: bias+scale, split hi/lo, scatter to [B,H,S,HD]
    const int g = lane >> 2, tig = lane & 3;
    #pragma unroll
    for (int mt = 0; mt < 4; mt++)
        #pragma unroll
        for (int nt = 0; nt < 4; nt++) {
            int col = n0 + wn*32 + nt*8 + tig*2;
            int h = col >> 6, d = col & 63;
            float b0 = bias[col], b1 = bias[col + 1];
            #pragma unroll
            for (int rr = 0; rr < 2; rr++) {
                int m = m0 + wm*64 + mt*16 + g + rr*8;
                int b = m >> 11, s = m & 2047;
                size_t off = ((size_t)((b*HH + h)*SS + s)) * HD + d;
                float v0 = (acc[mt][nt][rr*2 + 0] + b0) * scale;
                float v1 = (acc[mt][nt][rr*2 + 1] + b1) * scale;
                uint32_t hp, lp;
                packhl(v0, v1, hp, lp);
                *(uint32_t*)(Ch + off) = hp;
                *(uint32_t*)(Cl + off) = lp;
            }
        }
}

// ---------------- flash attention with bf16x3 mma ----------------
// CTA: 128 q-rows of one (b,h); 8 warps x 16 rows. KV tiles of 64.
#define KST 72    // K/V smem row stride (halves)

__global__ __launch_bounds__(256, 1)
void attn_mma(const __nv_bfloat16* __restrict__ qh, const __nv_bfloat16* __restrict__ ql,
              const __nv_bfloat16* __restrict__ kh, const __nv_bfloat16* __restrict__ kl,
              const __nv_bfloat16* __restrict__ vh, const __nv_bfloat16* __restrict__ vl,
              float* __restrict__ out)
{
    __shared__ __nv_bfloat16 smbuf[4*64*KST];
    __nv_bfloat16* Kh = smbuf;
    __nv_bfloat16* Kl = smbuf + 64*KST;
    __nv_bfloat16* Vh = smbuf + 2*64*KST;
    __nv_bfloat16* Vl = smbuf + 3*64*KST;
    const uint32_t Kh_b = (uint32_t)__cvta_generic_to_shared(Kh);
    const uint32_t Kl_b = (uint32_t)__cvta_generic_to_shared(Kl);
    const uint32_t Vh_b = (uint32_t)__cvta_generic_to_shared(Vh);
    const uint32_t Vl_b = (uint32_t)__cvta_generic_to_shared(Vl);

    const int tid  = threadIdx.x;
    const int lane = tid & 31;
    const int w    = tid >> 5;
    const int q0   = blockIdx.x * 128;
    const int bhI  = blockIdx.y;
    const int g    = lane >> 2, tig = lane & 3;

    const size_t hd_base = (size_t)bhI * SS * HD;

    // ---- load Q fragments (staged through smem, hi pass then lo pass) ----
    uint32_t qa_h[4][4], qa_l[4][4];
    {
        const uint32_t st_b = Kh_b;  // reuse Kh+Kl region (128*KST halves)
        __nv_bfloat16* stage = Kh;
        #pragma unroll
        for (int pass = 0; pass < 2; pass++) {
            const __nv_bfloat16* src = (pass == 0 ? qh : ql) + hd_base + (size_t)q0 * HD;
            for (int u = tid; u < 1024; u += 256) {
                int r = u >> 3, s8 = (u & 7) * 8;
                *(uint4*)&stage[r*KST + s8] = *(const uint4*)(src + r*HD + s8);
            }
            __syncthreads();
            #pragma unroll
            for (int kc = 0; kc < 4; kc++) {
                uint32_t off = (uint32_t)(((w*16 + (lane & 15)) * KST
                                           + kc*16 + (lane >> 4) * 8) * 2);
                if (pass == 0) ldsm_x4(qa_h[kc], st_b + off);
                else           ldsm_x4(qa_l[kc], st_b + off);
            }
            __syncthreads();
        }
    }

    float m0 = -1e4f, m1 = -1e4f, l0 = 0.0f, l1 = 0.0f;
    float o[8][4];
    #pragma unroll
    for (int nt = 0; nt < 8; nt++)
        #pragma unroll
        for (int j = 0; j < 4; j++) o[nt][j] = 0.0f;

    for (int kt = 0; kt < SS / 64; kt++) {
        __syncthreads();
        // load K,V tiles (64x64 each, hi+lo)
        #pragma unroll
        for (int j = 0; j < 2; j++) {
            int u = tid * 2 + j;
            int r = u >> 3, s8 = (u & 7) * 8;
            size_t gm = hd_base + (size_t)(kt*64 + r) * HD + s8;
            int so = r*KST + s8;
            *(uint4*)&Kh[so] = *(const uint4*)(kh + gm);
            *(uint4*)&Kl[so] = *(const uint4*)(kl + gm);
            *(uint4*)&Vh[so] = *(const uint4*)(vh + gm);
            *(uint4*)&Vl[so] = *(const uint4*)(vl + gm);
        }
        __syncthreads();

        // ---- S = Q K^T ----
        float sacc[8][4];
        #pragma unroll
        for (int nt = 0; nt < 8; nt++)
            #pragma unroll
            for (int j = 0; j < 4; j++) sacc[nt][j] = 0.0f;

        #pragma unroll
        for (int kc = 0; kc < 4; kc++) {
            uint32_t kbh[8][2], kbl[8][2];
            #pragma unroll
            for (int nt = 0; nt < 8; nt++) {
                // non-trans ldmatrix on row-major K gives the B=K^T fragment
                uint32_t off = (uint32_t)(((nt*8 + (lane & 7)) * KST
                                           + kc*16 + (lane & 8)) * 2);
                ldsm_x2(kbh[nt], Kh_b + off);
                ldsm_x2(kbl[nt], Kl_b + off);
            }
            #pragma unroll
            for (int nt = 0; nt < 8; nt++) {
                mma16816(sacc[nt], qa_h[kc], kbh[nt]);
                mma16816(sacc[nt], qa_h[kc], kbl[nt]);
                mma16816(sacc[nt], qa_l[kc], kbh[nt]);
            }
        }

        // ---- online softmax (S already in log2 units) ----
        float rm0 = -1e30f, rm1 = -1e30f;
        #pragma unroll
        for (int nt = 0; nt < 8; nt++) {
            rm0 = fmaxf(rm0, fmaxf(sacc[nt][0], sacc[nt][1]));
            rm1 = fmaxf(rm1, fmaxf(sacc[nt][2], sacc[nt][3]));
        }
        rm0 = fmaxf(rm0, __shfl_xor_sync(0xffffffffu, rm0, 1));
        rm0 = fmaxf(rm0, __shfl_xor_sync(0xffffffffu, rm0, 2));
        rm1 = fmaxf(rm1, __shfl_xor_sync(0xffffffffu, rm1, 1));
        rm1 = fmaxf(rm1, __shfl_xor_sync(0xffffffffu, rm1, 2));
        float nm0 = fmaxf(m0, rm0), nm1 = fmaxf(m1, rm1);
        float a0 = ex2(m0 - nm0), a1 = ex2(m1 - nm1);
        float rs0 = 0.0f, rs1 = 0.0f;
        #pragma unroll
        for (int nt = 0; nt < 8; nt++) {
            sacc[nt][0] = ex2(sacc[nt][0] - nm0);
            sacc[nt][1] = ex2(sacc[nt][1] - nm0);
            sacc[nt][2] = ex2(sacc[nt][2] - nm1);
            sacc[nt][3] = ex2(sacc[nt][3] - nm1);
            rs0 += sacc[nt][0] + sacc[nt][1];
            rs1 += sacc[nt][2] + sacc[nt][3];
        }
        rs0 += __shfl_xor_sync(0xffffffffu, rs0, 1);
        rs0 += __shfl_xor_sync(0xffffffffu, rs0, 2);
        rs1 += __shfl_xor_sync(0xffffffffu, rs1, 1);
        rs1 += __shfl_xor_sync(0xffffffffu, rs1, 2);
        l0 = l0 * a0 + rs0;  m0 = nm0;
        l1 = l1 * a1 + rs1;  m1 = nm1;
        #pragma unroll
        for (int nt = 0; nt < 8; nt++) {
            o[nt][0] *= a0; o[nt][1] *= a0;
            o[nt][2] *= a1; o[nt][3] *= a1;
        }

        // ---- P fragments (C-layout -> A-layout), hi/lo split ----
        uint32_t ph[4][4], pl[4][4];
        #pragma unroll
        for (int kc = 0; kc < 4; kc++) {
            packhl(sacc[2*kc][0],   sacc[2*kc][1],   ph[kc][0], pl[kc][0]);
            packhl(sacc[2*kc][2],   sacc[2*kc][3],   ph[kc][1], pl[kc][1]);
            packhl(sacc[2*kc+1][0], sacc[2*kc+1][1], ph[kc][2], pl[kc][2]);
            packhl(sacc[2*kc+1][2], sacc[2*kc+1][3], ph[kc][3], pl[kc][3]);
        }

        // ---- O += P V ----
        #pragma unroll
        for (int kc = 0; kc < 4; kc++) {
            uint32_t vbh[8][2], vbl[8][2];
            #pragma unroll
            for (int nt = 0; nt < 8; nt++) {
                uint32_t off = (uint32_t)(((kc*16 + (lane & 15)) * KST + nt*8) * 2);
                ldsm_x2t(vbh[nt], Vh_b + off);
                ldsm_x2t(vbl[nt], Vl_b + off);
            }
            #pragma unroll
            for (int nt = 0; nt < 8; nt++) {
                mma16816(o[nt], ph[kc], vbh[nt]);
                mma16816(o[nt], ph[kc], vbl[nt]);
                mma16816(o[nt], pl[kc], vbh[nt]);
            }
        }
    }

    // ---- epilogue: normalize, write [B,S,D] fp32 ----
    const int b = bhI >> 4, h = bhI & 15;
    const float inv0 = 1.0f / l0, inv1 = 1.0f / l1;
    const int s0 = q0 + w*16 + g;
    #pragma unroll
    for (int nt = 0; nt < 8; nt++) {
        int d = h*64 + nt*8 + tig*2;
        float2 r0 = make_float2(o[nt][0] * inv0, o[nt][1] * inv0);
        float2 r1 = make_float2(o[nt][2] * inv1, o[nt][3] * inv1);
        *(float2*)(out + ((size_t)(b*SS + s0))     * DD + d) = r0;
        *(float2*)(out + ((size_t)(b*SS + s0 + 8)) * DD + d) = r1;
    }
}

// ---------------------------------------------------------------------------
extern "C" void kernel_launch(void* const* d_in, const int* in_sizes, int n_in,
                              void* d_out, int out_size)
{
    (void)in_sizes; (void)n_in; (void)out_size;
    const float* x  = (const float*)d_in[0];
    const float* Wq = (const float*)d_in[1];
    const float* bq = (const float*)d_in[2];
    const float* Wk = (const float*)d_in[3];
    const float* bk = (const float*)d_in[4];
    const float* Wv = (const float*)d_in[5];
    const float* bv = (const float*)d_in[6];
    float* out = (float*)d_out;

    __nv_bfloat16 *xh, *xl, *wqh, *wql, *wkh, *wkl, *wvh, *wvl;
    __nv_bfloat16 *qhp, *qlp, *khp, *klp, *vhp, *vlp;
    cudaGetSymbolAddress((void**)&xh,  g_xh);  cudaGetSymbolAddress((void**)&xl,  g_xl);
    cudaGetSymbolAddress((void**)&wqh, g_wqh); cudaGetSymbolAddress((void**)&wql, g_wql);
    cudaGetSymbolAddress((void**)&wkh, g_wkh); cudaGetSymbolAddress((void**)&wkl, g_wkl);
    cudaGetSymbolAddress((void**)&wvh, g_wvh); cudaGetSymbolAddress((void**)&wvl, g_wvl);
    cudaGetSymbolAddress((void**)&qhp, g_qh);  cudaGetSymbolAddress((void**)&qlp, g_ql);
    cudaGetSymbolAddress((void**)&khp, g_kh);  cudaGetSymbolAddress((void**)&klp, g_kl);
    cudaGetSymbolAddress((void**)&vhp, g_vh);  cudaGetSymbolAddress((void**)&vlp, g_vl);

    split_kernel<<<(MM*DD)/4/256, 256>>>(x,  xh,  xl,  MM*DD);
    split_kernel<<<(DD*DD)/4/256, 256>>>(Wq, wqh, wql, DD*DD);
    split_kernel<<<(DD*DD)/4/256, 256>>>(Wk, wkh, wkl, DD*DD);
    split_kernel<<<(DD*DD)/4/256, 256>>>(Wv, wvh, wvl, DD*DD);

    dim3 ggrid(DD/128, MM/128);   // (8, 32)
    gemm_bf16x3<<<ggrid, 256>>>(xh, xl, wqh, wql, bq, qhp, qlp, QSCALE);
    gemm_bf16x3<<<ggrid, 256>>>(xh, xl, wkh, wkl, bk, khp, klp, 1.0f);
    gemm_bf16x3<<<ggrid, 256>>>(xh, xl, wvh, wvl, bv, vhp, vlp, 1.0f);

    dim3 agrid(SS/128, BB*HH);    // (16, 32)
    attn_mma<<<agrid, 256>>>(qhp, qlp, khp, klp, vhp, vlp, out);
}